// round 17
// baseline (speedup 1.0000x reference)
#include <cuda_runtime.h>
#include <cuda_fp16.h>
#include <math.h>
#include <stdint.h>

#define K_DIM 256
#define H_DIM 256
#define OUT_DIM 512
#define G_DIM 256
#define TILE_M 64
#define NTH 256
#define XTILE_BYTES 65536     // 64 rows x 256 fp32

// ---- smem layout (bytes) ----
#define ASTR_B 528            // 264 fp16 per A row
#define XSTG 0                // 65536: raw fp32 x tile staging
#define A_HI 65536            // 33792
#define PART 99328            // 2048
#define STAT 101376           // 512
#define SBID 101888           // 256
#define MBAR 102144           // 8
#define SMEM_TOTAL 102400

// ---------------- global scratch ----------------
__device__ float d_Wc[OUT_DIM * K_DIM];
__device__ float d_GAMMA[G_DIM * H_DIM];
__device__ float d_BETA[G_DIM * H_DIM];
// weight images in per-lane MMA-B-fragment order
__device__ __align__(128) uint8_t d_W1f[131072];
__device__ __align__(128) uint8_t d_W2f[131072];
__device__ __align__(128) uint8_t d_W3f[262144];

// ---------------- asm helpers ----------------
__device__ __forceinline__ uint32_t smem_u32(const void* p) {
    uint32_t a;
    asm("{ .reg .u64 t; cvta.to.shared.u64 t, %1; cvt.u32.u64 %0, t; }" : "=r"(a) : "l"(p));
    return a;
}
__device__ __forceinline__ void ldsm4(uint32_t (&r)[4], uint32_t a) {
    asm volatile("ldmatrix.sync.aligned.m8n8.x4.shared.b16 {%0,%1,%2,%3}, [%4];"
                 : "=r"(r[0]), "=r"(r[1]), "=r"(r[2]), "=r"(r[3]) : "r"(a));
}
__device__ __forceinline__ void mma16816(float* c, const uint32_t* a, uint32_t b0, uint32_t b1) {
    asm volatile("mma.sync.aligned.m16n8k16.row.col.f32.f16.f16.f32 "
                 "{%0,%1,%2,%3}, {%4,%5,%6,%7}, {%8,%9}, {%0,%1,%2,%3};"
                 : "+f"(c[0]), "+f"(c[1]), "+f"(c[2]), "+f"(c[3])
                 : "r"(a[0]), "r"(a[1]), "r"(a[2]), "r"(a[3]), "r"(b0), "r"(b1));
}
#define MBAR_INIT(mb, c) asm volatile("mbarrier.init.shared.b64 [%0], %1;" :: "r"(mb), "r"(c) : "memory")
__device__ __forceinline__ void mbar_wait(uint32_t mb, uint32_t parity) {
    asm volatile(
        "{\n\t.reg .pred P1;\n\tW_%=:\n\t"
        "mbarrier.try_wait.parity.acquire.cta.shared::cta.b64 P1, [%0], %1, 0x989680;\n\t"
        "@P1 bra.uni D_%=;\n\tbra.uni W_%=;\n\tD_%=:\n\t}"
        :: "r"(mb), "r"(parity) : "memory");
}
__device__ __forceinline__ void issue_x_copy(uint32_t sb, const float* src) {
    asm volatile("mbarrier.arrive.expect_tx.shared.b64 _, [%0], %1;"
                 :: "r"(sb + MBAR), "r"(XTILE_BYTES) : "memory");
    asm volatile("cp.async.bulk.shared::cta.global.mbarrier::complete_tx::bytes "
                 "[%0], [%1], %2, [%3];"
                 :: "r"(sb + XSTG), "l"(src), "r"(XTILE_BYTES), "r"(sb + MBAR)
                 : "memory");
}

// ---------------------------------------------------------------------------
// prep: all four weight norms in one launch; W1/2/3 stored in fragment order
// ---------------------------------------------------------------------------
__global__ void wn_all(const float* __restrict__ v_cond, const float* __restrict__ g_cond,
                       const float* __restrict__ v1, const float* __restrict__ g1,
                       const float* __restrict__ v2, const float* __restrict__ g2,
                       const float* __restrict__ v3, const float* __restrict__ g3) {
    int b = blockIdx.x, t = threadIdx.x;
    const float *v, *g;
    int which, r;
    if (b < 512)       { which = 0; r = b;        v = v_cond; g = g_cond; }
    else if (b < 768)  { which = 1; r = b - 512;  v = v1;     g = g1; }
    else if (b < 1024) { which = 2; r = b - 768;  v = v2;     g = g2; }
    else               { which = 3; r = b - 1024; v = v3;     g = g3; }

    float x = v[r * K_DIM + t];
    float ss = x * x;
#pragma unroll
    for (int o = 16; o; o >>= 1) ss += __shfl_xor_sync(0xffffffffu, ss, o);
    __shared__ float red[8];
    __shared__ float s_scale;
    if ((t & 31) == 0) red[t >> 5] = ss;
    __syncthreads();
    if (t == 0) {
        float tot = 0.f;
#pragma unroll
        for (int i = 0; i < 8; i++) tot += red[i];
        s_scale = g[r] / sqrtf(tot);
    }
    __syncthreads();
    float wv = x * s_scale;
    if (which == 0) { d_Wc[r * K_DIM + t] = wv; return; }
    uint8_t* img = (which == 1) ? d_W1f : (which == 2) ? d_W2f : d_W3f;
    int p = r >> 8, n = r & 255;
    int k = t;
    int t16 = k >> 4, G = n >> 4;
    int s_n = (n >> 3) & 1, n8v = n & 7;
    int half = (k >> 3) & 1, k8 = k & 7;
    int lanei = n8v * 4 + (k8 >> 1);
    int regi = s_n * 2 + half;
    size_t off = ((size_t)((t16 * 16 + G) * 32 + lanei) * 16) + regi * 4 + (k8 & 1) * 2;
    *reinterpret_cast<__half*>(img + (size_t)p * 131072 + off) = __float2half(wv);
}

__global__ void film_kernel(const float* __restrict__ cond, const float* __restrict__ b_cond) {
    __shared__ float cs[K_DIM];
    int g = blockIdx.x, t = threadIdx.x;
    cs[t] = cond[g * K_DIM + t];
    __syncthreads();
    const float* w0 = d_Wc + (size_t)t * K_DIM;
    const float* w1 = d_Wc + (size_t)(t + 256) * K_DIM;
    float a0 = 0.f, a1 = 0.f;
#pragma unroll 8
    for (int k = 0; k < K_DIM; k++) {
        float c = cs[k];
        a0 = fmaf(c, w0[k], a0);
        a1 = fmaf(c, w1[k], a1);
    }
    d_GAMMA[g * H_DIM + t] = a0 + b_cond[t] + 1.0f;
    d_BETA[g * H_DIM + t]  = a1 + b_cond[t + 256];
}

// ---------------------------------------------------------------------------
// one full GEMM pass, register double-buffered W fragments from L2
// ---------------------------------------------------------------------------
__device__ __forceinline__ void run_pass(uint32_t sb, const uint8_t* __restrict__ wimg,
                                         float (&acc)[2][8][4],
                                         int m0, int warp_n, int lane) {
#pragma unroll
    for (int i = 0; i < 2; i++)
#pragma unroll
        for (int j = 0; j < 8; j++)
#pragma unroll
            for (int qq = 0; qq < 4; qq++) acc[i][j][qq] = 0.f;

    const uint32_t abase = sb + A_HI + (m0 + (lane & 15)) * ASTR_B + (lane >> 4) * 16;
    const uint4* __restrict__ wbase =
        reinterpret_cast<const uint4*>(wimg) + (size_t)(warp_n * 4) * 32 + lane;

    uint4 wv[4];
#pragma unroll
    for (int g = 0; g < 4; g++) wv[g] = wbase[g * 32];

#pragma unroll
    for (int t = 0; t < 16; t++) {
        uint32_t ah0[4], ah1[4];
        uint32_t aoff = abase + t * 32;
        ldsm4(ah0, aoff);
        ldsm4(ah1, aoff + 16 * ASTR_B);
        uint4 wn[4];
        if (t < 15) {
#pragma unroll
            for (int g = 0; g < 4; g++) wn[g] = wbase[(t + 1) * 512 + g * 32];
        }
#pragma unroll
        for (int g = 0; g < 4; g++) {
            mma16816(acc[0][2 * g + 0], ah0, wv[g].x, wv[g].y);
            mma16816(acc[0][2 * g + 1], ah0, wv[g].z, wv[g].w);
            mma16816(acc[1][2 * g + 0], ah1, wv[g].x, wv[g].y);
            mma16816(acc[1][2 * g + 1], ah1, wv[g].z, wv[g].w);
        }
        if (t < 15) {
#pragma unroll
            for (int g = 0; g < 4; g++) wv[g] = wn[g];
        }
    }
}

// single-limb fp16 store into A at (row, k pair)
__device__ __forceinline__ void sts_single2(char* smem, int row, int k, float y0, float y1) {
    uint32_t off = row * ASTR_B + k * 2;
    *reinterpret_cast<__half2*>(smem + A_HI + off) =
        __halves2half2(__float2half_rn(y0), __float2half_rn(y1));
}

// ---------------------------------------------------------------------------
__global__ void __launch_bounds__(NTH, 2)
fused_mma(const float* __restrict__ x,
          const int* __restrict__ bids,
          const float* __restrict__ b2,
          const float* __restrict__ b3,
          float* __restrict__ out, int N, int ntiles) {
    extern __shared__ __align__(128) char smem[];
    const uint32_t sb = smem_u32(smem);
    const int tid = threadIdx.x;
    const int lane = tid & 31, w = tid >> 5;
    const int warp_m = w >> 2, warp_n = w & 3;    // 2 x 4 warps
    const int m0 = warp_m * 32, n0 = warp_n * 64;
    const int lgrp = lane >> 2, lq = lane & 3;
    const int grid = gridDim.x;

    if ((int)blockIdx.x >= ntiles) return;

    if (tid == 0) MBAR_INIT(sb + MBAR, 1);
    __syncthreads();
    if (tid == 0) issue_x_copy(sb, x + (size_t)blockIdx.x * TILE_M * K_DIM);

    float acc[2][8][4];
    int it = 0;

#pragma unroll 1
    for (int tile = blockIdx.x; tile < ntiles; tile += grid, it++) {
        const int row0 = tile * TILE_M;

        mbar_wait(sb + MBAR, it & 1);  // x staged
        __syncthreads();               // prev tile's GEMM3 reads of A complete

        // ---- bids prefetch + convert staged x -> A (fp16) ----
        if (tid < TILE_M) {
            int row = row0 + tid;
            *reinterpret_cast<int*>(smem + SBID + tid * 4) = (row < N) ? bids[row] : 0;
        }
#pragma unroll 4
        for (int i = 0; i < 16; i++) {
            int idx = tid + NTH * i;
            int m = idx >> 6, c4 = idx & 63;
            float4 v = *reinterpret_cast<const float4*>(smem + XSTG + (m * 64 + c4) * 16);
            sts_single2(smem, m, c4 * 4 + 0, v.x, v.y);
            sts_single2(smem, m, c4 * 4 + 2, v.z, v.w);
        }
        __syncthreads();               // A ready; XSTG fully consumed

        // prefetch next tile's x while the 4 GEMM passes run
        if (tid == 0 && tile + grid < ntiles)
            issue_x_copy(sb, x + (size_t)(tile + grid) * TILE_M * K_DIM);

        // ================= GEMM1 + layernorm/FiLM/relu =================
        run_pass(sb, d_W1f, acc, m0, warp_n, lane);
        {
#pragma unroll
            for (int mi = 0; mi < 2; mi++)
#pragma unroll
                for (int half = 0; half < 2; half++) {
                    float s = 0.f, ss = 0.f;
#pragma unroll
                    for (int j = 0; j < 8; j++) {
                        float v0 = acc[mi][j][half * 2 + 0];
                        float v1 = acc[mi][j][half * 2 + 1];
                        s += v0 + v1;
                        ss = fmaf(v0, v0, fmaf(v1, v1, ss));
                    }
                    s  += __shfl_xor_sync(0xffffffffu, s, 1);
                    s  += __shfl_xor_sync(0xffffffffu, s, 2);
                    ss += __shfl_xor_sync(0xffffffffu, ss, 1);
                    ss += __shfl_xor_sync(0xffffffffu, ss, 2);
                    if (lq == 0) {
                        int r = m0 + mi * 16 + half * 8 + lgrp;
                        *reinterpret_cast<float2*>(smem + PART + (r * 4 + warp_n) * 8) =
                            make_float2(s, ss);
                    }
                }
            __syncthreads();
            if (tid < TILE_M) {
                float s = 0.f, ss = 0.f;
#pragma unroll
                for (int qq = 0; qq < 4; qq++) {
                    float2 p = *reinterpret_cast<float2*>(smem + PART + (tid * 4 + qq) * 8);
                    s += p.x;
                    ss += p.y;
                }
                float mu = s * (1.f / 256.f);
                float var = ss * (1.f / 256.f) - mu * mu;
                float rstd = rsqrtf(var + 1e-5f);
                *reinterpret_cast<float2*>(smem + STAT + tid * 8) = make_float2(mu, rstd);
            }
            __syncthreads();
#pragma unroll
            for (int mi = 0; mi < 2; mi++)
#pragma unroll
                for (int half = 0; half < 2; half++) {
                    int r = m0 + mi * 16 + half * 8 + lgrp;
                    float2 st = *reinterpret_cast<float2*>(smem + STAT + r * 8);
                    int bid = *reinterpret_cast<int*>(smem + SBID + r * 4);
                    const float* gp = d_GAMMA + (size_t)bid * H_DIM;
                    const float* bp = d_BETA  + (size_t)bid * H_DIM;
#pragma unroll
                    for (int j = 0; j < 8; j++) {
                        int c = n0 + j * 8 + lq * 2;
                        float2 g2 = *reinterpret_cast<const float2*>(gp + c);
                        float2 be = *reinterpret_cast<const float2*>(bp + c);
                        float y0 = fmaxf(fmaf((acc[mi][j][half * 2 + 0] - st.x) * st.y, g2.x, be.x), 0.f);
                        float y1 = fmaxf(fmaf((acc[mi][j][half * 2 + 1] - st.x) * st.y, g2.y, be.y), 0.f);
                        sts_single2(smem, r, c, y0, y1);
                    }
                }
        }
        __syncthreads();   // A = h1 ready

        // ================= GEMM2 + relu + b2 =================
        run_pass(sb, d_W2f, acc, m0, warp_n, lane);
        __syncthreads();   // all warps done reading A
        {
#pragma unroll
            for (int mi = 0; mi < 2; mi++)
#pragma unroll
                for (int half = 0; half < 2; half++) {
                    int r = m0 + mi * 16 + half * 8 + lgrp;
#pragma unroll
                    for (int j = 0; j < 8; j++) {
                        int c = n0 + j * 8 + lq * 2;
                        float2 bb = *reinterpret_cast<const float2*>(b2 + c);
                        float y0 = fmaxf(acc[mi][j][half * 2 + 0] + bb.x, 0.f);
                        float y1 = fmaxf(acc[mi][j][half * 2 + 1] + bb.y, 0.f);
                        sts_single2(smem, r, c, y0, y1);
                    }
                }
        }
        __syncthreads();   // A = h2 ready

        // ================= GEMM3 (two 256-col halves) + b3 -> out =====
#pragma unroll 1
        for (int hf = 0; hf < 2; hf++) {
            run_pass(sb, d_W3f + (size_t)hf * 131072, acc, m0, warp_n, lane);
#pragma unroll
            for (int mi = 0; mi < 2; mi++)
#pragma unroll
                for (int half = 0; half < 2; half++) {
                    int r = m0 + mi * 16 + half * 8 + lgrp;
                    int row = row0 + r;
                    if (row < N) {
                        float* op = out + (size_t)row * OUT_DIM + hf * 256;
#pragma unroll
                        for (int j = 0; j < 8; j++) {
                            int c = n0 + j * 8 + lq * 2;
                            float2 bb = *reinterpret_cast<const float2*>(b3 + hf * 256 + c);
                            float2 o2;
                            o2.x = acc[mi][j][half * 2 + 0] + bb.x;
                            o2.y = acc[mi][j][half * 2 + 1] + bb.y;
                            *reinterpret_cast<float2*>(op + c) = o2;
                        }
                    }
                }
        }
    }
}

// ---------------------------------------------------------------------------
extern "C" void kernel_launch(void* const* d_in, const int* in_sizes, int n_in,
                              void* d_out, int out_size) {
    const float* x         = (const float*)d_in[0];
    const float* cond      = (const float*)d_in[1];
    const int*   batch_ids = (const int*)  d_in[2];
    const float* v_cond    = (const float*)d_in[3];
    const float* g_cond    = (const float*)d_in[4];
    const float* b_cond    = (const float*)d_in[5];
    const float* v1        = (const float*)d_in[6];
    const float* g1        = (const float*)d_in[7];
    const float* v2        = (const float*)d_in[8];
    const float* g2        = (const float*)d_in[9];
    const float* b2        = (const float*)d_in[10];
    const float* v3        = (const float*)d_in[11];
    const float* g3        = (const float*)d_in[12];
    const float* b3        = (const float*)d_in[13];
    float* out = (float*)d_out;

    int N = in_sizes[0] / K_DIM;
    int ntiles = (N + TILE_M - 1) / TILE_M;

    wn_all<<<1536, 256>>>(v_cond, g_cond, v1, g1, v2, g2, v3, g3);
    film_kernel<<<G_DIM, 256>>>(cond, b_cond);

    int dev = 0, nsm = 148;
    cudaGetDevice(&dev);
    cudaDeviceGetAttribute(&nsm, cudaDevAttrMultiProcessorCount, dev);
    int grid = 2 * nsm;
    if (grid > ntiles) grid = ntiles;

    cudaFuncSetAttribute(fused_mma, cudaFuncAttributeMaxDynamicSharedMemorySize, SMEM_TOTAL);
    fused_mma<<<grid, NTH, SMEM_TOTAL>>>(x, batch_ids, b2, b3, out, N, ntiles);
}